// round 2
// baseline (speedup 1.0000x reference)
#include <cuda_runtime.h>

// Problem-shape constants (fixed by the dataset)
#define NN     100000
#define EE     1000000
#define GGR    1024
#define FF     44
#define HMAX   88

// ---------------- scratch (static __device__, no allocation) ----------------
__device__ int   g_cnt[NN];
__device__ int   g_cur[NN];
__device__ int   g_rowptr[NN + 1];
__device__ int   g_col[EE];
__device__ float g_dinv[NN];
__device__ __align__(16) float g_bufA[(size_t)NN * HMAX];
__device__ __align__(16) float g_bufB[(size_t)NN * HMAX];
__device__ __align__(16) float g_pooled[GGR * FF];
__device__ int   g_bsum[128];

// ---------------- CSR build ----------------
__global__ void k_zero(int n) {
    int i = blockIdx.x * blockDim.x + threadIdx.x;
    if (i < n) { g_cnt[i] = 0; g_cur[i] = 0; }
}

__global__ void k_deg(const int* __restrict__ dst, int e) {
    int i = blockIdx.x * blockDim.x + threadIdx.x;
    if (i < e) atomicAdd(&g_cnt[dst[i]], 1);
}

__global__ void k_dinv(int n) {
    int i = blockIdx.x * blockDim.x + threadIdx.x;
    if (i < n) g_dinv[i] = rsqrtf((float)(g_cnt[i] + 1));  // +1 self loop
}

__global__ void k_scanA(int n) {
    __shared__ int s[1024];
    int t = threadIdx.x;
    int gid = blockIdx.x * 1024 + t;
    int v = (gid < n) ? g_cnt[gid] : 0;
    s[t] = v;
    __syncthreads();
    for (int off = 1; off < 1024; off <<= 1) {
        int x = (t >= off) ? s[t - off] : 0;
        __syncthreads();
        s[t] += x;
        __syncthreads();
    }
    if (gid < n) g_rowptr[gid] = s[t] - v;   // exclusive
    if (t == 1023) g_bsum[blockIdx.x] = s[1023];
}

__global__ void k_scanB(int nb) {
    if (threadIdx.x == 0 && blockIdx.x == 0) {
        int run = 0;
        for (int b = 0; b < nb; b++) { int x = g_bsum[b]; g_bsum[b] = run; run += x; }
    }
}

__global__ void k_scanC(int n, int e) {
    int gid = blockIdx.x * 1024 + threadIdx.x;
    if (gid < n) g_rowptr[gid] += g_bsum[blockIdx.x];
    if (gid == 0) g_rowptr[n] = e;
}

__global__ void k_fill(const int* __restrict__ src, const int* __restrict__ dst, int e) {
    int i = blockIdx.x * blockDim.x + threadIdx.x;
    if (i < e) {
        int d = dst[i];
        int p = atomicAdd(&g_cur[d], 1);
        g_col[g_rowptr[d] + p] = src[i];
    }
}

// ---------------- GEMM with dinv-scaled epilogue: out = dinv[i] * (in @ W) ----------------
// warp handles 4 nodes; lanes cover FOUT (with stride-32 sub-outputs)
template <int FIN, int FOUT>
__global__ void k_gemm(const float* __restrict__ in, const float* __restrict__ W,
                       float* __restrict__ out, int n) {
    constexpr int M = (FOUT + 31) / 32;
    __shared__ float Ws[FIN * FOUT];
    __shared__ float xs[32][FIN];

    for (int i = threadIdx.x; i < FIN * FOUT; i += blockDim.x) Ws[i] = W[i];

    int warp = threadIdx.x >> 5;
    int lane = threadIdx.x & 31;
    int nodeBase = (blockIdx.x * 8 + warp) * 4;

    #pragma unroll
    for (int a = 0; a < 4; a++) {
        int node = nodeBase + a;
        if (node < n) {
            for (int k = lane; k < FIN; k += 32)
                xs[warp * 4 + a][k] = in[(size_t)node * FIN + k];
        }
    }
    __syncthreads();

    float acc[4][M];
    #pragma unroll
    for (int a = 0; a < 4; a++)
        #pragma unroll
        for (int m = 0; m < M; m++) acc[a][m] = 0.f;

    #pragma unroll 4
    for (int k = 0; k < FIN; k++) {
        float wv[M];
        #pragma unroll
        for (int m = 0; m < M; m++) {
            int j = lane + 32 * m;
            wv[m] = (j < FOUT) ? Ws[k * FOUT + j] : 0.f;
        }
        #pragma unroll
        for (int a = 0; a < 4; a++) {
            float xk = xs[warp * 4 + a][k];
            #pragma unroll
            for (int m = 0; m < M; m++) acc[a][m] += xk * wv[m];
        }
    }

    #pragma unroll
    for (int a = 0; a < 4; a++) {
        int node = nodeBase + a;
        if (node < n) {
            float dv = g_dinv[node];
            #pragma unroll
            for (int m = 0; m < M; m++) {
                int j = lane + 32 * m;
                if (j < FOUT) out[(size_t)node * FOUT + j] = dv * acc[a][m];
            }
        }
    }
}

// ---------------- aggregation: out[i] = relu(dinv[i]*(sum_in g[src] + g[i]) + b) ----------------
template <int FOUT>
__global__ void k_agg(const float* __restrict__ g, const float* __restrict__ bias,
                      float* __restrict__ out, int n) {
    constexpr int NV = FOUT / 4;
    int warp = threadIdx.x >> 5;
    int lane = threadIdx.x & 31;
    int node = blockIdx.x * 8 + warp;
    if (node >= n) return;
    if (lane >= NV) return;

    int beg = g_rowptr[node];
    int end = g_rowptr[node + 1];

    const float4* g4 = (const float4*)g;
    float4 acc = g4[(size_t)node * NV + lane];  // self-loop term
    for (int e = beg; e < end; e++) {
        int s = g_col[e];
        float4 v = g4[(size_t)s * NV + lane];
        acc.x += v.x; acc.y += v.y; acc.z += v.z; acc.w += v.w;
    }
    float dv = g_dinv[node];
    float4 b = ((const float4*)bias)[lane];
    float4 o;
    o.x = fmaxf(dv * acc.x + b.x, 0.f);
    o.y = fmaxf(dv * acc.y + b.y, 0.f);
    o.z = fmaxf(dv * acc.z + b.z, 0.f);
    o.w = fmaxf(dv * acc.w + b.w, 0.f);
    ((float4*)out)[(size_t)node * NV + lane] = o;
}

// ---------------- global max pool (batch sorted -> contiguous segments) ----------------
__device__ __forceinline__ int lower_bound_dev(const int* a, int n, int key) {
    int lo = 0, hi = n;
    while (lo < hi) {
        int m = (lo + hi) >> 1;
        if (a[m] < key) lo = m + 1; else hi = m;
    }
    return lo;
}

__global__ void k_pool(const int* __restrict__ batch, const float* __restrict__ h,
                       int n, int gcount) {
    constexpr int NV = FF / 4;  // 11
    int warp = threadIdx.x >> 5;
    int lane = threadIdx.x & 31;
    int gidx = blockIdx.x * 8 + warp;
    if (gidx >= gcount) return;

    int beg = lower_bound_dev(batch, n, gidx);
    int end = lower_bound_dev(batch, n, gidx + 1);
    if (lane >= NV) return;

    const float4* h4 = (const float4*)h;
    float4 m = make_float4(0.f, 0.f, 0.f, 0.f);  // relu outputs are >= 0
    for (int r = beg; r < end; r++) {
        float4 v = h4[(size_t)r * NV + lane];
        m.x = fmaxf(m.x, v.x); m.y = fmaxf(m.y, v.y);
        m.z = fmaxf(m.z, v.z); m.w = fmaxf(m.w, v.w);
    }
    ((float4*)g_pooled)[gidx * NV + lane] = m;
}

// ---------------- head 1: out[g] = relu(pooled[g] . Wg + bg) ----------------
__global__ void k_x1(const float* __restrict__ Wg, const float* __restrict__ bg,
                     float* __restrict__ out, int gcount) {
    int warp = threadIdx.x >> 5;
    int lane = threadIdx.x & 31;
    int gidx = blockIdx.x * 8 + warp;
    if (gidx >= gcount) return;
    float v = 0.f;
    for (int k = lane; k < FF; k += 32) v += g_pooled[gidx * FF + k] * Wg[k];
    #pragma unroll
    for (int o = 16; o; o >>= 1) v += __shfl_down_sync(0xffffffffu, v, o);
    if (lane == 0) out[gidx] = fmaxf(v + bg[0], 0.f);
}

// ---------------- head 2: out[g] += relu(feat @ Wf1 + bf1) @ Wf2 + bf2 ----------------
// block = 128 threads (one per hidden unit), 8 graphs per block
__global__ void k_mlp(const float* __restrict__ feat, const float* __restrict__ Wf1,
                      const float* __restrict__ bf1, const float* __restrict__ Wf2,
                      const float* __restrict__ bf2, float* __restrict__ out,
                      int gcount, int featd) {
    __shared__ __align__(16) float fs[8 * 1024];  // featd <= 1024
    __shared__ float red[8][4];
    int g0 = blockIdx.x * 8;
    int tid = threadIdx.x;

    for (int idx = tid; idx < 8 * featd; idx += 128) {
        int k = idx >> 3, gg = idx & 7;
        fs[idx] = (g0 + gg < gcount) ? feat[(size_t)(g0 + gg) * featd + k] : 0.f;
    }
    __syncthreads();

    float acc[8];
    #pragma unroll
    for (int gg = 0; gg < 8; gg++) acc[gg] = 0.f;

    for (int k = 0; k < featd; k++) {
        float wv = Wf1[(size_t)k * 128 + tid];
        float4 f0 = *(const float4*)&fs[k * 8];
        float4 f1 = *(const float4*)&fs[k * 8 + 4];
        acc[0] += f0.x * wv; acc[1] += f0.y * wv;
        acc[2] += f0.z * wv; acc[3] += f0.w * wv;
        acc[4] += f1.x * wv; acc[5] += f1.y * wv;
        acc[6] += f1.z * wv; acc[7] += f1.w * wv;
    }

    float b1v = bf1[tid];
    float w2v = Wf2[tid];
    int lane = tid & 31, w = tid >> 5;
    #pragma unroll
    for (int gg = 0; gg < 8; gg++) {
        float v = fmaxf(acc[gg] + b1v, 0.f) * w2v;
        #pragma unroll
        for (int o = 16; o; o >>= 1) v += __shfl_down_sync(0xffffffffu, v, o);
        if (lane == 0) red[gg][w] = v;
    }
    __syncthreads();
    if (tid < 8 && g0 + tid < gcount) {
        float x2 = red[tid][0] + red[tid][1] + red[tid][2] + red[tid][3] + bf2[0];
        out[g0 + tid] += x2;
    }
}

// ---------------- launch ----------------
extern "C" void kernel_launch(void* const* d_in, const int* in_sizes, int n_in,
                              void* d_out, int out_size) {
    const float* x       = (const float*)d_in[0];
    const int*   ei      = (const int*)d_in[1];
    const int*   batch   = (const int*)d_in[2];
    const float* feature = (const float*)d_in[3];
    const float* W1 = (const float*)d_in[4];
    const float* b1 = (const float*)d_in[5];
    const float* W2 = (const float*)d_in[6];
    const float* b2 = (const float*)d_in[7];
    const float* W3 = (const float*)d_in[8];
    const float* b3 = (const float*)d_in[9];
    const float* Wg = (const float*)d_in[10];
    const float* bg = (const float*)d_in[11];
    const float* Wf1 = (const float*)d_in[12];
    const float* bf1 = (const float*)d_in[13];
    const float* Wf2 = (const float*)d_in[14];
    const float* bf2 = (const float*)d_in[15];
    float* out = (float*)d_out;

    int n = in_sizes[2];           // N nodes (batch array length)
    int e = in_sizes[1] / 2;       // E edges
    int g = out_size;              // G graphs
    int featd = in_sizes[3] / g;   // FEAT

    const int* src = ei;
    const int* dst = ei + e;

    float *pA, *pB;
    cudaGetSymbolAddress((void**)&pA, g_bufA);
    cudaGetSymbolAddress((void**)&pB, g_bufB);

    // CSR build + normalization
    k_zero<<<(n + 255) / 256, 256>>>(n);
    k_deg<<<(e + 255) / 256, 256>>>(dst, e);
    k_dinv<<<(n + 255) / 256, 256>>>(n);
    int nb = (n + 1023) / 1024;
    k_scanA<<<nb, 1024>>>(n);
    k_scanB<<<1, 32>>>(nb);
    k_scanC<<<nb, 1024>>>(n, e);
    k_fill<<<(e + 255) / 256, 256>>>(src, dst, e);

    // GCN layers
    int gb = (n + 31) / 32;  // 32 nodes per block (8 warps x 4)
    int ab = (n + 7) / 8;    // 8 nodes per block (warp per node)
    k_gemm<44, 44><<<gb, 256>>>(x,  W1, pA, n);
    k_agg<44><<<ab, 256>>>(pA, b1, pB, n);
    k_gemm<44, 88><<<gb, 256>>>(pB, W2, pA, n);
    k_agg<88><<<ab, 256>>>(pA, b2, pB, n);
    k_gemm<88, 44><<<gb, 256>>>(pB, W3, pA, n);
    k_agg<44><<<ab, 256>>>(pA, b3, pB, n);

    // pool + heads
    k_pool<<<(g + 7) / 8, 256>>>(batch, pB, n, g);
    k_x1<<<(g + 7) / 8, 256>>>(Wg, bg, out, g);
    k_mlp<<<(g + 7) / 8, 128>>>(feature, Wf1, bf1, Wf2, bf2, out, g, featd);
}

// round 3
// speedup vs baseline: 1.0822x; 1.0822x over previous
#include <cuda_runtime.h>

// Problem-shape constants (fixed by the dataset)
#define NN     100000
#define EE     1000000
#define GGR    1024
#define FF     44
#define HMAX   88

// ---------------- scratch (static __device__, zero-initialized at load) ----------------
__device__ int   g_cnt[NN];       // zeroed at load; re-zeroed by k_agg (layer 1) each launch
__device__ int   g_cur[NN];       // same
__device__ int   g_rowptr[NN + 1];
__device__ int   g_col[EE];
__device__ float g_dinv[NN];
__device__ __align__(16) float g_bufA[(size_t)NN * HMAX];
__device__ __align__(16) float g_bufB[(size_t)NN * HMAX];
__device__ int   g_bsum[128];

// ---------------- CSR build ----------------
__global__ void k_deg(const int* __restrict__ dst, int e) {
    int i = blockIdx.x * blockDim.x + threadIdx.x;
    if (i < e) atomicAdd(&g_cnt[dst[i]], 1);
}

// block scan (exclusive within block) + per-block sums + dinv
__global__ void k_scanA(int n) {
    __shared__ int s[1024];
    int t = threadIdx.x;
    int gid = blockIdx.x * 1024 + t;
    int v = (gid < n) ? g_cnt[gid] : 0;
    if (gid < n) g_dinv[gid] = rsqrtf((float)(v + 1));  // +1 self loop
    s[t] = v;
    __syncthreads();
    for (int off = 1; off < 1024; off <<= 1) {
        int x = (t >= off) ? s[t - off] : 0;
        __syncthreads();
        s[t] += x;
        __syncthreads();
    }
    if (gid < n) g_rowptr[gid] = s[t] - v;   // exclusive
    if (t == 1023) g_bsum[blockIdx.x] = s[1023];
}

// parallel exclusive scan of the (<=128) block sums
__global__ void k_scanB(int nb) {
    int t = threadIdx.x;           // 128 threads
    int lane = t & 31, w = t >> 5;
    int v = (t < nb) ? g_bsum[t] : 0;
    int x = v;
    #pragma unroll
    for (int off = 1; off < 32; off <<= 1) {
        int y = __shfl_up_sync(0xffffffffu, x, off);
        if (lane >= off) x += y;
    }
    __shared__ int ws[4];
    if (lane == 31) ws[w] = x;
    __syncthreads();
    int add = 0;
    for (int i = 0; i < w; i++) add += ws[i];
    x += add;
    if (t < nb) g_bsum[t] = x - v;  // exclusive
}

__global__ void k_scanC(int n, int e) {
    int gid = blockIdx.x * 1024 + threadIdx.x;
    if (gid < n) g_rowptr[gid] += g_bsum[blockIdx.x];
    if (gid == 0) g_rowptr[n] = e;
}

__global__ void k_fill(const int* __restrict__ src, const int* __restrict__ dst, int e) {
    int i = blockIdx.x * blockDim.x + threadIdx.x;
    if (i < e) {
        int d = dst[i];
        int p = atomicAdd(&g_cur[d], 1);
        g_col[g_rowptr[d] + p] = src[i];
    }
}

// ---------------- GEMM with dinv-scaled epilogue: out = dinv[i] * (in @ W) ----------------
// warp handles 8 nodes; lanes cover FOUT (stride-32 sub-outputs)
template <int FIN, int FOUT>
__global__ void k_gemm(const float* __restrict__ in, const float* __restrict__ W,
                       float* __restrict__ out, int n) {
    constexpr int M = (FOUT + 31) / 32;
    __shared__ float Ws[FIN * FOUT];
    __shared__ float xs[64][FIN];

    for (int i = threadIdx.x; i < FIN * FOUT; i += blockDim.x) Ws[i] = W[i];

    int warp = threadIdx.x >> 5;
    int lane = threadIdx.x & 31;
    int nodeBase = blockIdx.x * 64 + warp * 8;

    #pragma unroll
    for (int a = 0; a < 8; a++) {
        int node = nodeBase + a;
        if (node < n) {
            for (int k = lane; k < FIN; k += 32)
                xs[warp * 8 + a][k] = in[(size_t)node * FIN + k];
        }
    }
    __syncthreads();

    float acc[8][M];
    #pragma unroll
    for (int a = 0; a < 8; a++)
        #pragma unroll
        for (int m = 0; m < M; m++) acc[a][m] = 0.f;

    #pragma unroll 4
    for (int k = 0; k < FIN; k++) {
        float wv[M];
        #pragma unroll
        for (int m = 0; m < M; m++) {
            int j = lane + 32 * m;
            wv[m] = (j < FOUT) ? Ws[k * FOUT + j] : 0.f;
        }
        #pragma unroll
        for (int a = 0; a < 8; a++) {
            float xk = xs[warp * 8 + a][k];
            #pragma unroll
            for (int m = 0; m < M; m++) acc[a][m] += xk * wv[m];
        }
    }

    #pragma unroll
    for (int a = 0; a < 8; a++) {
        int node = nodeBase + a;
        if (node < n) {
            float dv = g_dinv[node];
            #pragma unroll
            for (int m = 0; m < M; m++) {
                int j = lane + 32 * m;
                if (j < FOUT) out[(size_t)node * FOUT + j] = dv * acc[a][m];
            }
        }
    }
}

// ---------------- aggregation: out[i] = relu(dinv[i]*(sum_in g[src] + g[i]) + b) ----------------
// 4-way edge unroll to expose memory-level parallelism.
template <int FOUT>
__global__ void k_agg(const float* __restrict__ g, const float* __restrict__ bias,
                      float* __restrict__ out, int n, int clean) {
    constexpr int NV = FOUT / 4;
    int warp = threadIdx.x >> 5;
    int lane = threadIdx.x & 31;
    int node = blockIdx.x * 8 + warp;
    if (node >= n) return;
    if (clean && lane == 0) { g_cnt[node] = 0; g_cur[node] = 0; }  // reset for next replay
    if (lane >= NV) return;

    int beg = g_rowptr[node];
    int end = g_rowptr[node + 1];

    const float4* g4 = (const float4*)g;
    float4 acc = g4[(size_t)node * NV + lane];  // self-loop term
    int e = beg;
    for (; e + 4 <= end; e += 4) {
        int s0 = g_col[e + 0];
        int s1 = g_col[e + 1];
        int s2 = g_col[e + 2];
        int s3 = g_col[e + 3];
        float4 v0 = g4[(size_t)s0 * NV + lane];
        float4 v1 = g4[(size_t)s1 * NV + lane];
        float4 v2 = g4[(size_t)s2 * NV + lane];
        float4 v3 = g4[(size_t)s3 * NV + lane];
        acc.x += (v0.x + v1.x) + (v2.x + v3.x);
        acc.y += (v0.y + v1.y) + (v2.y + v3.y);
        acc.z += (v0.z + v1.z) + (v2.z + v3.z);
        acc.w += (v0.w + v1.w) + (v2.w + v3.w);
    }
    for (; e < end; e++) {
        int s = g_col[e];
        float4 v = g4[(size_t)s * NV + lane];
        acc.x += v.x; acc.y += v.y; acc.z += v.z; acc.w += v.w;
    }
    float dv = g_dinv[node];
    float4 b = ((const float4*)bias)[lane];
    float4 o;
    o.x = fmaxf(dv * acc.x + b.x, 0.f);
    o.y = fmaxf(dv * acc.y + b.y, 0.f);
    o.z = fmaxf(dv * acc.z + b.z, 0.f);
    o.w = fmaxf(dv * acc.w + b.w, 0.f);
    ((float4*)out)[(size_t)node * NV + lane] = o;
}

// ---------------- fused global max pool + head1: out[g] = relu(max_pool . Wg + bg) ----------------
__device__ __forceinline__ int lower_bound_dev(const int* a, int n, int key) {
    int lo = 0, hi = n;
    while (lo < hi) {
        int m = (lo + hi) >> 1;
        if (a[m] < key) lo = m + 1; else hi = m;
    }
    return lo;
}

__global__ void k_poolx1(const int* __restrict__ batch, const float* __restrict__ h,
                         const float* __restrict__ Wg, const float* __restrict__ bg,
                         float* __restrict__ out, int n, int gcount) {
    constexpr int NV = FF / 4;  // 11
    int warp = threadIdx.x >> 5;
    int lane = threadIdx.x & 31;
    int gidx = blockIdx.x * 8 + warp;
    if (gidx >= gcount) return;

    int beg = lower_bound_dev(batch, n, gidx);
    int end = lower_bound_dev(batch, n, gidx + 1);

    float part = 0.f;
    if (lane < NV) {
        const float4* h4 = (const float4*)h;
        float4 m = make_float4(0.f, 0.f, 0.f, 0.f);  // relu outputs are >= 0
        int r = beg;
        for (; r + 2 <= end; r += 2) {
            float4 v0 = h4[(size_t)r * NV + lane];
            float4 v1 = h4[(size_t)(r + 1) * NV + lane];
            m.x = fmaxf(m.x, fmaxf(v0.x, v1.x));
            m.y = fmaxf(m.y, fmaxf(v0.y, v1.y));
            m.z = fmaxf(m.z, fmaxf(v0.z, v1.z));
            m.w = fmaxf(m.w, fmaxf(v0.w, v1.w));
        }
        for (; r < end; r++) {
            float4 v = h4[(size_t)r * NV + lane];
            m.x = fmaxf(m.x, v.x); m.y = fmaxf(m.y, v.y);
            m.z = fmaxf(m.z, v.z); m.w = fmaxf(m.w, v.w);
        }
        float4 w4 = ((const float4*)Wg)[lane];
        part = m.x * w4.x + m.y * w4.y + m.z * w4.z + m.w * w4.w;
    }
    #pragma unroll
    for (int o = 16; o; o >>= 1) part += __shfl_down_sync(0xffffffffu, part, o);
    if (lane == 0) out[gidx] = fmaxf(part + bg[0], 0.f);
}

// ---------------- head 2: out[g] += relu(feat @ Wf1 + bf1) @ Wf2 + bf2 ----------------
// 256 threads: hidden unit = tid&127, k-range split by tid>>7. 8 graphs per block.
__global__ void k_mlp(const float* __restrict__ feat, const float* __restrict__ Wf1,
                      const float* __restrict__ bf1, const float* __restrict__ Wf2,
                      const float* __restrict__ bf2, float* __restrict__ out,
                      int gcount, int featd) {
    __shared__ __align__(16) float fs[8 * 1024];  // featd <= 1024
    __shared__ float part[128 * 8];
    __shared__ float red[8][4];
    int g0 = blockIdx.x * 8;
    int tid = threadIdx.x;

    for (int idx = tid; idx < 8 * featd; idx += 256) {
        int k = idx >> 3, gg = idx & 7;
        fs[idx] = (g0 + gg < gcount) ? feat[(size_t)(g0 + gg) * featd + k] : 0.f;
    }
    __syncthreads();

    int hid = tid & 127;
    int half = tid >> 7;
    int k0 = half ? (featd / 2) : 0;
    int k1 = half ? featd : (featd / 2);

    float acc[8];
    #pragma unroll
    for (int gg = 0; gg < 8; gg++) acc[gg] = 0.f;

    #pragma unroll 4
    for (int k = k0; k < k1; k++) {
        float wv = Wf1[(size_t)k * 128 + hid];
        float4 f0 = *(const float4*)&fs[k * 8];
        float4 f1 = *(const float4*)&fs[k * 8 + 4];
        acc[0] += f0.x * wv; acc[1] += f0.y * wv;
        acc[2] += f0.z * wv; acc[3] += f0.w * wv;
        acc[4] += f1.x * wv; acc[5] += f1.y * wv;
        acc[6] += f1.z * wv; acc[7] += f1.w * wv;
    }

    if (half == 1) {
        #pragma unroll
        for (int gg = 0; gg < 8; gg++) part[hid * 8 + gg] = acc[gg];
    }
    __syncthreads();

    if (half == 0) {
        float b1v = bf1[hid];
        float w2v = Wf2[hid];
        int lane = hid & 31, w = hid >> 5;
        #pragma unroll
        for (int gg = 0; gg < 8; gg++) {
            float v = fmaxf(acc[gg] + part[hid * 8 + gg] + b1v, 0.f) * w2v;
            #pragma unroll
            for (int o = 16; o; o >>= 1) v += __shfl_down_sync(0xffffffffu, v, o);
            if (lane == 0) red[gg][w] = v;
        }
    }
    __syncthreads();
    if (tid < 8 && g0 + tid < gcount) {
        float x2 = red[tid][0] + red[tid][1] + red[tid][2] + red[tid][3] + bf2[0];
        out[g0 + tid] += x2;
    }
}

// ---------------- launch ----------------
extern "C" void kernel_launch(void* const* d_in, const int* in_sizes, int n_in,
                              void* d_out, int out_size) {
    const float* x       = (const float*)d_in[0];
    const int*   ei      = (const int*)d_in[1];
    const int*   batch   = (const int*)d_in[2];
    const float* feature = (const float*)d_in[3];
    const float* W1 = (const float*)d_in[4];
    const float* b1 = (const float*)d_in[5];
    const float* W2 = (const float*)d_in[6];
    const float* b2 = (const float*)d_in[7];
    const float* W3 = (const float*)d_in[8];
    const float* b3 = (const float*)d_in[9];
    const float* Wg = (const float*)d_in[10];
    const float* bg = (const float*)d_in[11];
    const float* Wf1 = (const float*)d_in[12];
    const float* bf1 = (const float*)d_in[13];
    const float* Wf2 = (const float*)d_in[14];
    const float* bf2 = (const float*)d_in[15];
    float* out = (float*)d_out;

    int n = in_sizes[2];           // N nodes (batch array length)
    int e = in_sizes[1] / 2;       // E edges
    int g = out_size;              // G graphs
    int featd = in_sizes[3] / g;   // FEAT

    const int* src = ei;
    const int* dst = ei + e;

    float *pA, *pB;
    cudaGetSymbolAddress((void**)&pA, g_bufA);
    cudaGetSymbolAddress((void**)&pB, g_bufB);

    // CSR build + normalization (g_cnt/g_cur are zero on entry: zero-init at
    // load, and re-zeroed by the first k_agg on every launch)
    k_deg<<<(e + 255) / 256, 256>>>(dst, e);
    int nb = (n + 1023) / 1024;
    k_scanA<<<nb, 1024>>>(n);
    k_scanB<<<1, 128>>>(nb);
    k_scanC<<<nb, 1024>>>(n, e);
    k_fill<<<(e + 255) / 256, 256>>>(src, dst, e);

    // GCN layers
    int gb = (n + 63) / 64;  // 64 nodes per block (8 warps x 8)
    int ab = (n + 7) / 8;    // 8 nodes per block (warp per node)
    k_gemm<44, 44><<<gb, 256>>>(x,  W1, pA, n);
    k_agg<44><<<ab, 256>>>(pA, b1, pB, n, 1);
    k_gemm<44, 88><<<gb, 256>>>(pB, W2, pA, n);
    k_agg<88><<<ab, 256>>>(pA, b2, pB, n, 0);
    k_gemm<88, 44><<<gb, 256>>>(pB, W3, pA, n);
    k_agg<44><<<ab, 256>>>(pA, b3, pB, n, 0);

    // pool + heads
    k_poolx1<<<(g + 7) / 8, 256>>>(batch, pB, Wg, bg, out, n, g);
    k_mlp<<<(g + 7) / 8, 256>>>(feature, Wf1, bf1, Wf2, bf2, out, g, featd);
}

// round 8
// speedup vs baseline: 1.1452x; 1.0582x over previous
#include <cuda_runtime.h>

// Problem-shape constants (fixed by the dataset)
#define NN     100000
#define EE     1000000
#define GGR    1024
#define FF     44
#define HMAX   88

// ---------------- scratch (static __device__, zero-initialized at load) ----------------
__device__ int   g_cnt[NN];       // zeroed at load; re-zeroed by agg1 each launch
__device__ int   g_cur[NN];       // same
__device__ int   g_rowptr[NN + 1];
__device__ int   g_col[EE];
__device__ float g_dinv[NN];
__device__ __align__(16) float g_bufA[(size_t)NN * HMAX];
__device__ __align__(16) float g_bufB[(size_t)NN * HMAX];
__device__ float g_x2[GGR];
__device__ int   g_bsum[128];

// ---------------- CSR build ----------------
__global__ void k_deg(const int* __restrict__ dst, int e) {
    int i = blockIdx.x * blockDim.x + threadIdx.x;
    if (i < e) atomicAdd(&g_cnt[dst[i]], 1);
}

// block scan (exclusive within block) + per-block sums + dinv
__global__ void k_scanA(int n) {
    __shared__ int s[1024];
    int t = threadIdx.x;
    int gid = blockIdx.x * 1024 + t;
    int v = (gid < n) ? g_cnt[gid] : 0;
    if (gid < n) g_dinv[gid] = rsqrtf((float)(v + 1));  // +1 self loop
    s[t] = v;
    __syncthreads();
    for (int off = 1; off < 1024; off <<= 1) {
        int x = (t >= off) ? s[t - off] : 0;
        __syncthreads();
        s[t] += x;
        __syncthreads();
    }
    if (gid < n) g_rowptr[gid] = s[t] - v;   // exclusive
    if (t == 1023) g_bsum[blockIdx.x] = s[1023];
}

// parallel exclusive scan of the (<=128) block sums
__global__ void k_scanB(int nb) {
    int t = threadIdx.x;           // 128 threads
    int lane = t & 31, w = t >> 5;
    int v = (t < nb) ? g_bsum[t] : 0;
    int x = v;
    #pragma unroll
    for (int off = 1; off < 32; off <<= 1) {
        int y = __shfl_up_sync(0xffffffffu, x, off);
        if (lane >= off) x += y;
    }
    __shared__ int ws[4];
    if (lane == 31) ws[w] = x;
    __syncthreads();
    int add = 0;
    for (int i = 0; i < w; i++) add += ws[i];
    x += add;
    if (t < nb) g_bsum[t] = x - v;  // exclusive
}

__global__ void k_scanC(int n, int e) {
    int gid = blockIdx.x * 1024 + threadIdx.x;
    if (gid < n) g_rowptr[gid] += g_bsum[blockIdx.x];
    if (gid == 0) g_rowptr[n] = e;
}

__global__ void k_fill(const int* __restrict__ src, const int* __restrict__ dst, int e) {
    int i = blockIdx.x * blockDim.x + threadIdx.x;
    if (i < e) {
        int d = dst[i];
        int p = atomicAdd(&g_cur[d], 1);
        g_col[g_rowptr[d] + p] = src[i];
    }
}

// ---------------- GEMM: out = [dinv[i] *] (in @ W) ----------------
// warp handles 8 nodes; lanes cover FOUT (stride-32 sub-outputs)
template <int FIN, int FOUT, int SCALE>
__global__ void k_gemm(const float* __restrict__ in, const float* __restrict__ W,
                       float* __restrict__ out, int n) {
    constexpr int M = (FOUT + 31) / 32;
    __shared__ float Ws[FIN * FOUT];
    __shared__ float xs[64][FIN];

    for (int i = threadIdx.x; i < FIN * FOUT; i += blockDim.x) Ws[i] = W[i];

    int warp = threadIdx.x >> 5;
    int lane = threadIdx.x & 31;
    int nodeBase = blockIdx.x * 64 + warp * 8;

    #pragma unroll
    for (int a = 0; a < 8; a++) {
        int node = nodeBase + a;
        if (node < n) {
            for (int k = lane; k < FIN; k += 32)
                xs[warp * 8 + a][k] = in[(size_t)node * FIN + k];
        }
    }
    __syncthreads();

    float acc[8][M];
    #pragma unroll
    for (int a = 0; a < 8; a++)
        #pragma unroll
        for (int m = 0; m < M; m++) acc[a][m] = 0.f;

    #pragma unroll 4
    for (int k = 0; k < FIN; k++) {
        float wv[M];
        #pragma unroll
        for (int m = 0; m < M; m++) {
            int j = lane + 32 * m;
            wv[m] = (j < FOUT) ? Ws[k * FOUT + j] : 0.f;
        }
        #pragma unroll
        for (int a = 0; a < 8; a++) {
            float xk = xs[warp * 8 + a][k];
            #pragma unroll
            for (int m = 0; m < M; m++) acc[a][m] += xk * wv[m];
        }
    }

    #pragma unroll
    for (int a = 0; a < 8; a++) {
        int node = nodeBase + a;
        if (node < n) {
            float dv = SCALE ? g_dinv[node] : 1.f;
            #pragma unroll
            for (int m = 0; m < M; m++) {
                int j = lane + 32 * m;
                if (j < FOUT) out[(size_t)node * FOUT + j] = SCALE ? dv * acc[a][m]
                                                                   : acc[a][m];
            }
        }
    }
}

// ---------------- aggregation, FOUT=44: 2 nodes per warp ----------------
// SRCSCALE=1: g rows are UNscaled; multiply each gathered row by dinv[src].
// SRCSCALE=0: g rows already carry dinv[src].
// out[i] = relu(dinv[i]*(sum + self) + b)
template <int SRCSCALE>
__global__ void k_agg44(const float* __restrict__ g, const float* __restrict__ bias,
                        float* __restrict__ out, int n, int clean) {
    constexpr int NV = 11;                 // 44 floats = 11 float4
    int warp = threadIdx.x >> 5;
    int lane = threadIdx.x & 31;
    int half = lane >> 4;                  // 0 or 1
    int hl   = lane & 15;
    int node = blockIdx.x * 16 + warp * 2 + half;
    if (node >= n) return;
    if (clean && hl == 0) { g_cnt[node] = 0; g_cur[node] = 0; }  // reset for replays
    if (hl >= NV) return;

    int beg = g_rowptr[node];
    int end = g_rowptr[node + 1];

    const float4* g4 = (const float4*)g;
    float dvn = g_dinv[node];
    float4 acc = g4[(size_t)node * NV + hl];          // self-loop term
    if (SRCSCALE) { acc.x *= dvn; acc.y *= dvn; acc.z *= dvn; acc.w *= dvn; }

    int e = beg;
    for (; e + 4 <= end; e += 4) {
        int s0 = g_col[e + 0], s1 = g_col[e + 1], s2 = g_col[e + 2], s3 = g_col[e + 3];
        float4 v0 = g4[(size_t)s0 * NV + hl];
        float4 v1 = g4[(size_t)s1 * NV + hl];
        float4 v2 = g4[(size_t)s2 * NV + hl];
        float4 v3 = g4[(size_t)s3 * NV + hl];
        if (SRCSCALE) {
            float d0 = g_dinv[s0], d1 = g_dinv[s1], d2 = g_dinv[s2], d3 = g_dinv[s3];
            acc.x += (d0 * v0.x + d1 * v1.x) + (d2 * v2.x + d3 * v3.x);
            acc.y += (d0 * v0.y + d1 * v1.y) + (d2 * v2.y + d3 * v3.y);
            acc.z += (d0 * v0.z + d1 * v1.z) + (d2 * v2.z + d3 * v3.z);
            acc.w += (d0 * v0.w + d1 * v1.w) + (d2 * v2.w + d3 * v3.w);
        } else {
            acc.x += (v0.x + v1.x) + (v2.x + v3.x);
            acc.y += (v0.y + v1.y) + (v2.y + v3.y);
            acc.z += (v0.z + v1.z) + (v2.z + v3.z);
            acc.w += (v0.w + v1.w) + (v2.w + v3.w);
        }
    }
    for (; e < end; e++) {
        int s = g_col[e];
        float4 v = g4[(size_t)s * NV + hl];
        float d = SRCSCALE ? g_dinv[s] : 1.f;
        acc.x += d * v.x; acc.y += d * v.y; acc.z += d * v.z; acc.w += d * v.w;
    }
    float4 b = ((const float4*)bias)[hl];
    float4 o;
    o.x = fmaxf(dvn * acc.x + b.x, 0.f);
    o.y = fmaxf(dvn * acc.y + b.y, 0.f);
    o.z = fmaxf(dvn * acc.z + b.z, 0.f);
    o.w = fmaxf(dvn * acc.w + b.w, 0.f);
    ((float4*)out)[(size_t)node * NV + hl] = o;
}

// ---------------- aggregation, FOUT=88: warp per node (22 lanes of float4) ----------------
__global__ void k_agg88(const float* __restrict__ g, const float* __restrict__ bias,
                        float* __restrict__ out, int n) {
    constexpr int NV = 22;
    int warp = threadIdx.x >> 5;
    int lane = threadIdx.x & 31;
    int node = blockIdx.x * 8 + warp;
    if (node >= n) return;
    if (lane >= NV) return;

    int beg = g_rowptr[node];
    int end = g_rowptr[node + 1];

    const float4* g4 = (const float4*)g;
    float4 acc = g4[(size_t)node * NV + lane];  // self-loop term
    int e = beg;
    for (; e + 4 <= end; e += 4) {
        int s0 = g_col[e + 0], s1 = g_col[e + 1], s2 = g_col[e + 2], s3 = g_col[e + 3];
        float4 v0 = g4[(size_t)s0 * NV + lane];
        float4 v1 = g4[(size_t)s1 * NV + lane];
        float4 v2 = g4[(size_t)s2 * NV + lane];
        float4 v3 = g4[(size_t)s3 * NV + lane];
        acc.x += (v0.x + v1.x) + (v2.x + v3.x);
        acc.y += (v0.y + v1.y) + (v2.y + v3.y);
        acc.z += (v0.z + v1.z) + (v2.z + v3.z);
        acc.w += (v0.w + v1.w) + (v2.w + v3.w);
    }
    for (; e < end; e++) {
        int s = g_col[e];
        float4 v = g4[(size_t)s * NV + lane];
        acc.x += v.x; acc.y += v.y; acc.z += v.z; acc.w += v.w;
    }
    float dv = g_dinv[node];
    float4 b = ((const float4*)bias)[lane];
    float4 o;
    o.x = fmaxf(dv * acc.x + b.x, 0.f);
    o.y = fmaxf(dv * acc.y + b.y, 0.f);
    o.z = fmaxf(dv * acc.z + b.z, 0.f);
    o.w = fmaxf(dv * acc.w + b.w, 0.f);
    ((float4*)out)[(size_t)node * NV + lane] = o;
}

// ---------------- fused pool + head1 + combine: out[g]=relu(max.Wg+bg)+x2[g] ----------------
__device__ __forceinline__ int lower_bound_dev(const int* a, int n, int key) {
    int lo = 0, hi = n;
    while (lo < hi) {
        int m = (lo + hi) >> 1;
        if (a[m] < key) lo = m + 1; else hi = m;
    }
    return lo;
}

__global__ void k_poolx1(const int* __restrict__ batch, const float* __restrict__ h,
                         const float* __restrict__ Wg, const float* __restrict__ bg,
                         float* __restrict__ out, int n, int gcount) {
    constexpr int NV = FF / 4;  // 11
    int warp = threadIdx.x >> 5;
    int lane = threadIdx.x & 31;
    int gidx = blockIdx.x * 8 + warp;
    if (gidx >= gcount) return;

    int beg = lower_bound_dev(batch, n, gidx);
    int end = lower_bound_dev(batch, n, gidx + 1);

    float part = 0.f;
    if (lane < NV) {
        const float4* h4 = (const float4*)h;
        float4 m = make_float4(0.f, 0.f, 0.f, 0.f);  // relu outputs are >= 0
        int r = beg;
        for (; r + 2 <= end; r += 2) {
            float4 v0 = h4[(size_t)r * NV + lane];
            float4 v1 = h4[(size_t)(r + 1) * NV + lane];
            m.x = fmaxf(m.x, fmaxf(v0.x, v1.x));
            m.y = fmaxf(m.y, fmaxf(v0.y, v1.y));
            m.z = fmaxf(m.z, fmaxf(v0.z, v1.z));
            m.w = fmaxf(m.w, fmaxf(v0.w, v1.w));
        }
        for (; r < end; r++) {
            float4 v = h4[(size_t)r * NV + lane];
            m.x = fmaxf(m.x, v.x); m.y = fmaxf(m.y, v.y);
            m.z = fmaxf(m.z, v.z); m.w = fmaxf(m.w, v.w);
        }
        float4 w4 = ((const float4*)Wg)[lane];
        part = m.x * w4.x + m.y * w4.y + m.z * w4.z + m.w * w4.w;
    }
    #pragma unroll
    for (int o = 16; o; o >>= 1) part += __shfl_down_sync(0xffffffffu, part, o);
    if (lane == 0) out[gidx] = fmaxf(part + bg[0], 0.f) + g_x2[gidx];
}

// ---------------- head 2: x2[g] = relu(feat @ Wf1 + bf1) @ Wf2 + bf2 ----------------
// 256 threads: hidden unit = tid&127, k-range split by tid>>7. 8 graphs per block.
__global__ void k_mlp(const float* __restrict__ feat, const float* __restrict__ Wf1,
                      const float* __restrict__ bf1, const float* __restrict__ Wf2,
                      const float* __restrict__ bf2, int gcount, int featd) {
    __shared__ __align__(16) float fs[8 * 1024];  // featd <= 1024
    __shared__ float part[128 * 8];
    __shared__ float red[8][4];
    int g0 = blockIdx.x * 8;
    int tid = threadIdx.x;

    for (int idx = tid; idx < 8 * featd; idx += 256) {
        int k = idx >> 3, gg = idx & 7;
        fs[idx] = (g0 + gg < gcount) ? feat[(size_t)(g0 + gg) * featd + k] : 0.f;
    }
    __syncthreads();

    int hid = tid & 127;
    int half = tid >> 7;
    int k0 = half ? (featd / 2) : 0;
    int k1 = half ? featd : (featd / 2);

    float acc[8];
    #pragma unroll
    for (int gg = 0; gg < 8; gg++) acc[gg] = 0.f;

    #pragma unroll 4
    for (int k = k0; k < k1; k++) {
        float wv = Wf1[(size_t)k * 128 + hid];
        float4 f0 = *(const float4*)&fs[k * 8];
        float4 f1 = *(const float4*)&fs[k * 8 + 4];
        acc[0] += f0.x * wv; acc[1] += f0.y * wv;
        acc[2] += f0.z * wv; acc[3] += f0.w * wv;
        acc[4] += f1.x * wv; acc[5] += f1.y * wv;
        acc[6] += f1.z * wv; acc[7] += f1.w * wv;
    }

    if (half == 1) {
        #pragma unroll
        for (int gg = 0; gg < 8; gg++) part[hid * 8 + gg] = acc[gg];
    }
    __syncthreads();

    if (half == 0) {
        float b1v = bf1[hid];
        float w2v = Wf2[hid];
        int lane = hid & 31, w = hid >> 5;
        #pragma unroll
        for (int gg = 0; gg < 8; gg++) {
            float v = fmaxf(acc[gg] + part[hid * 8 + gg] + b1v, 0.f) * w2v;
            #pragma unroll
            for (int o = 16; o; o >>= 1) v += __shfl_down_sync(0xffffffffu, v, o);
            if (lane == 0) red[gg][w] = v;
        }
    }
    __syncthreads();
    if (tid < 8 && g0 + tid < gcount)
        g_x2[g0 + tid] = red[tid][0] + red[tid][1] + red[tid][2] + red[tid][3] + bf2[0];
}

// ---------------- launch ----------------
extern "C" void kernel_launch(void* const* d_in, const int* in_sizes, int n_in,
                              void* d_out, int out_size) {
    const float* x       = (const float*)d_in[0];
    const int*   ei      = (const int*)d_in[1];
    const int*   batch   = (const int*)d_in[2];
    const float* feature = (const float*)d_in[3];
    const float* W1 = (const float*)d_in[4];
    const float* b1 = (const float*)d_in[5];
    const float* W2 = (const float*)d_in[6];
    const float* b2 = (const float*)d_in[7];
    const float* W3 = (const float*)d_in[8];
    const float* b3 = (const float*)d_in[9];
    const float* Wg = (const float*)d_in[10];
    const float* bg = (const float*)d_in[11];
    const float* Wf1 = (const float*)d_in[12];
    const float* bf1 = (const float*)d_in[13];
    const float* Wf2 = (const float*)d_in[14];
    const float* bf2 = (const float*)d_in[15];
    float* out = (float*)d_out;

    int n = in_sizes[2];           // N nodes (batch array length)
    int e = in_sizes[1] / 2;       // E edges
    int g = out_size;              // G graphs
    int featd = in_sizes[3] / g;   // FEAT

    const int* src = ei;
    const int* dst = ei + e;

    float *pA, *pB;
    cudaGetSymbolAddress((void**)&pA, g_bufA);
    cudaGetSymbolAddress((void**)&pB, g_bufB);

    int nb  = (n + 1023) / 1024;
    int gb  = (n + 63) / 64;       // gemm: 64 nodes per block
    int ab1 = (n + 15) / 16;       // agg44: 16 nodes per block
    int ab2 = (n + 7) / 8;         // agg88: 8 nodes per block

    // CSR build; gemm1 (unscaled, CSR-independent) placed at launch index 3
    // so the profiler's fixed capture slot lands on a heavy kernel.
    k_deg<<<(e + 255) / 256, 256>>>(dst, e);                 // 0
    k_scanA<<<nb, 1024>>>(n);                                // 1
    k_scanB<<<1, 128>>>(nb);                                 // 2
    k_gemm<44, 44, 0><<<gb, 256>>>(x, W1, pA, n);            // 3  <- profiled
    k_scanC<<<nb, 1024>>>(n, e);                             // 4
    k_fill<<<(e + 255) / 256, 256>>>(src, dst, e);           // 5

    // GCN layers
    k_agg44<1><<<ab1, 256>>>(pA, b1, pB, n, 1);              // 6 (applies dinv[src])
    k_gemm<44, 88, 1><<<gb, 256>>>(pB, W2, pA, n);           // 7
    k_agg88<<<ab2, 256>>>(pA, b2, pB, n);                    // 8
    k_gemm<88, 44, 1><<<gb, 256>>>(pB, W3, pA, n);           // 9
    k_agg44<0><<<ab1, 256>>>(pA, b3, pB, n, 0);              // 10

    // heads
    k_mlp<<<(g + 7) / 8, 256>>>(feature, Wf1, bf1, Wf2, bf2, g, featd);  // 11
    k_poolx1<<<(g + 7) / 8, 256>>>(batch, pB, Wg, bg, out, n, g);        // 12
}

// round 13
// speedup vs baseline: 1.2222x; 1.0673x over previous
#include <cuda_runtime.h>
#include <cstdint>

// Problem-shape constants (fixed by the dataset)
#define NN     100000
#define EE     1000000
#define GGR    1024
#define FF     44
#define HMAX   88

// ---------------- scratch (static __device__, zero-initialized at load) ----------------
__device__ int   g_cnt[NN];       // zeroed at load; re-zeroed by agg1 each launch
__device__ int   g_cur[NN];       // same
__device__ int   g_rowptr[NN + 1];
__device__ int   g_col[EE];
__device__ float g_dinv[NN];
__device__ __align__(16) float g_bufA[(size_t)NN * HMAX];
__device__ __align__(16) float g_bufB[(size_t)NN * HMAX];
__device__ float g_x2[GGR];
__device__ int   g_bsum[128];

// ---------------- CSR build ----------------
__global__ void k_deg(const int* __restrict__ dst, int e) {
    int i = blockIdx.x * blockDim.x + threadIdx.x;
    if (i < e) atomicAdd(&g_cnt[dst[i]], 1);
}

__global__ void k_scanA(int n) {
    __shared__ int s[1024];
    int t = threadIdx.x;
    int gid = blockIdx.x * 1024 + t;
    int v = (gid < n) ? g_cnt[gid] : 0;
    if (gid < n) g_dinv[gid] = rsqrtf((float)(v + 1));  // +1 self loop
    s[t] = v;
    __syncthreads();
    for (int off = 1; off < 1024; off <<= 1) {
        int x = (t >= off) ? s[t - off] : 0;
        __syncthreads();
        s[t] += x;
        __syncthreads();
    }
    if (gid < n) g_rowptr[gid] = s[t] - v;   // exclusive
    if (t == 1023) g_bsum[blockIdx.x] = s[1023];
}

__global__ void k_scanB(int nb) {
    int t = threadIdx.x;           // 128 threads
    int lane = t & 31, w = t >> 5;
    int v = (t < nb) ? g_bsum[t] : 0;
    int x = v;
    #pragma unroll
    for (int off = 1; off < 32; off <<= 1) {
        int y = __shfl_up_sync(0xffffffffu, x, off);
        if (lane >= off) x += y;
    }
    __shared__ int ws[4];
    if (lane == 31) ws[w] = x;
    __syncthreads();
    int add = 0;
    for (int i = 0; i < w; i++) add += ws[i];
    x += add;
    if (t < nb) g_bsum[t] = x - v;  // exclusive
}

__global__ void k_scanC(int n, int e) {
    int gid = blockIdx.x * 1024 + threadIdx.x;
    if (gid < n) g_rowptr[gid] += g_bsum[blockIdx.x];
    if (gid == 0) g_rowptr[n] = e;
}

__global__ void k_fill(const int* __restrict__ src, const int* __restrict__ dst, int e) {
    int i = blockIdx.x * blockDim.x + threadIdx.x;
    if (i < e) {
        int d = dst[i];
        int p = atomicAdd(&g_cur[d], 1);
        g_col[g_rowptr[d] + p] = src[i];
    }
}

// ---------------- GEMM: out = [dinv[i] *] (in @ W) ----------------
// One node per thread. x transposed in smem (padded stride -> conflict-free),
// W broadcast from smem as ulonglong2 (LDS.128, N=1), accumulation via packed
// fma.rn.f32x2 (2 output cols per instruction -> half the fma-pipe issue).
template <int FIN, int FOUT, int SCALE, int NPB>
__global__ void __launch_bounds__(NPB) k_gemm2(const float* __restrict__ in,
                                               const float* __restrict__ W,
                                               float* __restrict__ out, int n) {
    constexpr int NP2 = FOUT / 2;        // f32x2 accumulators
    constexpr int F4  = FIN / 4;         // float4 per input row
    constexpr int XS  = NPB + 1;         // padded stride (conflict-free)
    __shared__ __align__(16) float Ws[FIN * FOUT];
    __shared__ float xs[FIN * XS];

    int tid = threadIdx.x;
    int node0 = blockIdx.x * NPB;

    // stage W (row-major [FIN][FOUT])
    for (int i = tid; i < FIN * FOUT / 4; i += NPB)
        ((float4*)Ws)[i] = ((const float4*)W)[i];

    // stage x transposed: xs[k * XS + r] = in[node0 + r][k]
    for (int f = tid; f < NPB * F4; f += NPB) {
        int r = f / F4, c4 = f % F4;
        int node = node0 + r;
        float4 v = (node < n) ? ((const float4*)in)[(size_t)node * F4 + c4]
                              : make_float4(0.f, 0.f, 0.f, 0.f);
        xs[(c4 * 4 + 0) * XS + r] = v.x;
        xs[(c4 * 4 + 1) * XS + r] = v.y;
        xs[(c4 * 4 + 2) * XS + r] = v.z;
        xs[(c4 * 4 + 3) * XS + r] = v.w;
    }
    __syncthreads();

    unsigned long long acc[NP2];
    #pragma unroll
    for (int j = 0; j < NP2; j++) acc[j] = 0ULL;

    #pragma unroll 4
    for (int k = 0; k < FIN; k++) {
        float xk = xs[k * XS + tid];
        unsigned long long x2;
        asm("mov.b64 %0, {%1, %1};" : "=l"(x2) : "r"(__float_as_uint(xk)));
        const ulonglong2* wrow = (const ulonglong2*)&Ws[k * FOUT];
        #pragma unroll
        for (int j2 = 0; j2 < NP2 / 2; j2++) {
            ulonglong2 w = wrow[j2];
            asm("fma.rn.f32x2 %0, %1, %2, %0;" : "+l"(acc[2 * j2 + 0]) : "l"(x2), "l"(w.x));
            asm("fma.rn.f32x2 %0, %1, %2, %0;" : "+l"(acc[2 * j2 + 1]) : "l"(x2), "l"(w.y));
        }
    }

    int node = node0 + tid;
    if (node < n) {
        float dv = SCALE ? g_dinv[node] : 1.f;
        float4* o4 = (float4*)(out + (size_t)node * FOUT);
        #pragma unroll
        for (int j = 0; j < NP2; j += 2) {
            unsigned int a, b, c, d;
            asm("mov.b64 {%0,%1}, %2;" : "=r"(a), "=r"(b) : "l"(acc[j]));
            asm("mov.b64 {%0,%1}, %2;" : "=r"(c), "=r"(d) : "l"(acc[j + 1]));
            float4 v = make_float4(dv * __uint_as_float(a), dv * __uint_as_float(b),
                                   dv * __uint_as_float(c), dv * __uint_as_float(d));
            o4[j >> 1] = v;
        }
    }
}

// ---------------- aggregation, FOUT=44: 2 nodes per warp ----------------
// SRCSCALE=1: g rows are UNscaled; multiply each gathered row by dinv[src].
// out[i] = relu(dinv[i]*(sum + self) + b)
template <int SRCSCALE>
__global__ void k_agg44(const float* __restrict__ g, const float* __restrict__ bias,
                        float* __restrict__ out, int n, int clean) {
    constexpr int NV = 11;                 // 44 floats = 11 float4
    int warp = threadIdx.x >> 5;
    int lane = threadIdx.x & 31;
    int half = lane >> 4;
    int hl   = lane & 15;
    int node = blockIdx.x * 16 + warp * 2 + half;
    if (node >= n) return;
    if (clean && hl == 0) { g_cnt[node] = 0; g_cur[node] = 0; }  // reset for replays
    if (hl >= NV) return;

    int beg = g_rowptr[node];
    int end = g_rowptr[node + 1];

    const float4* g4 = (const float4*)g;
    float dvn = g_dinv[node];
    float4 acc = g4[(size_t)node * NV + hl];          // self-loop term
    if (SRCSCALE) { acc.x *= dvn; acc.y *= dvn; acc.z *= dvn; acc.w *= dvn; }

    int e = beg;
    for (; e + 4 <= end; e += 4) {
        int s0 = g_col[e + 0], s1 = g_col[e + 1], s2 = g_col[e + 2], s3 = g_col[e + 3];
        float4 v0 = g4[(size_t)s0 * NV + hl];
        float4 v1 = g4[(size_t)s1 * NV + hl];
        float4 v2 = g4[(size_t)s2 * NV + hl];
        float4 v3 = g4[(size_t)s3 * NV + hl];
        if (SRCSCALE) {
            float d0 = g_dinv[s0], d1 = g_dinv[s1], d2 = g_dinv[s2], d3 = g_dinv[s3];
            acc.x += (d0 * v0.x + d1 * v1.x) + (d2 * v2.x + d3 * v3.x);
            acc.y += (d0 * v0.y + d1 * v1.y) + (d2 * v2.y + d3 * v3.y);
            acc.z += (d0 * v0.z + d1 * v1.z) + (d2 * v2.z + d3 * v3.z);
            acc.w += (d0 * v0.w + d1 * v1.w) + (d2 * v2.w + d3 * v3.w);
        } else {
            acc.x += (v0.x + v1.x) + (v2.x + v3.x);
            acc.y += (v0.y + v1.y) + (v2.y + v3.y);
            acc.z += (v0.z + v1.z) + (v2.z + v3.z);
            acc.w += (v0.w + v1.w) + (v2.w + v3.w);
        }
    }
    for (; e < end; e++) {
        int s = g_col[e];
        float4 v = g4[(size_t)s * NV + hl];
        float d = SRCSCALE ? g_dinv[s] : 1.f;
        acc.x += d * v.x; acc.y += d * v.y; acc.z += d * v.z; acc.w += d * v.w;
    }
    float4 b = ((const float4*)bias)[hl];
    float4 o;
    o.x = fmaxf(dvn * acc.x + b.x, 0.f);
    o.y = fmaxf(dvn * acc.y + b.y, 0.f);
    o.z = fmaxf(dvn * acc.z + b.z, 0.f);
    o.w = fmaxf(dvn * acc.w + b.w, 0.f);
    ((float4*)out)[(size_t)node * NV + hl] = o;
}

// ---------------- aggregation, FOUT=88: warp per node ----------------
__global__ void k_agg88(const float* __restrict__ g, const float* __restrict__ bias,
                        float* __restrict__ out, int n) {
    constexpr int NV = 22;
    int warp = threadIdx.x >> 5;
    int lane = threadIdx.x & 31;
    int node = blockIdx.x * 8 + warp;
    if (node >= n) return;
    if (lane >= NV) return;

    int beg = g_rowptr[node];
    int end = g_rowptr[node + 1];

    const float4* g4 = (const float4*)g;
    float4 acc = g4[(size_t)node * NV + lane];  // self-loop term
    int e = beg;
    for (; e + 4 <= end; e += 4) {
        int s0 = g_col[e + 0], s1 = g_col[e + 1], s2 = g_col[e + 2], s3 = g_col[e + 3];
        float4 v0 = g4[(size_t)s0 * NV + lane];
        float4 v1 = g4[(size_t)s1 * NV + lane];
        float4 v2 = g4[(size_t)s2 * NV + lane];
        float4 v3 = g4[(size_t)s3 * NV + lane];
        acc.x += (v0.x + v1.x) + (v2.x + v3.x);
        acc.y += (v0.y + v1.y) + (v2.y + v3.y);
        acc.z += (v0.z + v1.z) + (v2.z + v3.z);
        acc.w += (v0.w + v1.w) + (v2.w + v3.w);
    }
    for (; e < end; e++) {
        int s = g_col[e];
        float4 v = g4[(size_t)s * NV + lane];
        acc.x += v.x; acc.y += v.y; acc.z += v.z; acc.w += v.w;
    }
    float dv = g_dinv[node];
    float4 b = ((const float4*)bias)[lane];
    float4 o;
    o.x = fmaxf(dv * acc.x + b.x, 0.f);
    o.y = fmaxf(dv * acc.y + b.y, 0.f);
    o.z = fmaxf(dv * acc.z + b.z, 0.f);
    o.w = fmaxf(dv * acc.w + b.w, 0.f);
    ((float4*)out)[(size_t)node * NV + lane] = o;
}

// ---------------- fused pool + head1 + combine ----------------
__device__ __forceinline__ int lower_bound_dev(const int* a, int n, int key) {
    int lo = 0, hi = n;
    while (lo < hi) {
        int m = (lo + hi) >> 1;
        if (a[m] < key) lo = m + 1; else hi = m;
    }
    return lo;
}

__global__ void k_poolx1(const int* __restrict__ batch, const float* __restrict__ h,
                         const float* __restrict__ Wg, const float* __restrict__ bg,
                         float* __restrict__ out, int n, int gcount) {
    constexpr int NV = FF / 4;  // 11
    int warp = threadIdx.x >> 5;
    int lane = threadIdx.x & 31;
    int gidx = blockIdx.x * 8 + warp;
    if (gidx >= gcount) return;

    int beg = lower_bound_dev(batch, n, gidx);
    int end = lower_bound_dev(batch, n, gidx + 1);

    float part = 0.f;
    if (lane < NV) {
        const float4* h4 = (const float4*)h;
        float4 m = make_float4(0.f, 0.f, 0.f, 0.f);
        int r = beg;
        for (; r + 2 <= end; r += 2) {
            float4 v0 = h4[(size_t)r * NV + lane];
            float4 v1 = h4[(size_t)(r + 1) * NV + lane];
            m.x = fmaxf(m.x, fmaxf(v0.x, v1.x));
            m.y = fmaxf(m.y, fmaxf(v0.y, v1.y));
            m.z = fmaxf(m.z, fmaxf(v0.z, v1.z));
            m.w = fmaxf(m.w, fmaxf(v0.w, v1.w));
        }
        for (; r < end; r++) {
            float4 v = h4[(size_t)r * NV + lane];
            m.x = fmaxf(m.x, v.x); m.y = fmaxf(m.y, v.y);
            m.z = fmaxf(m.z, v.z); m.w = fmaxf(m.w, v.w);
        }
        float4 w4 = ((const float4*)Wg)[lane];
        part = m.x * w4.x + m.y * w4.y + m.z * w4.z + m.w * w4.w;
    }
    #pragma unroll
    for (int o = 16; o; o >>= 1) part += __shfl_down_sync(0xffffffffu, part, o);
    if (lane == 0) out[gidx] = fmaxf(part + bg[0], 0.f) + g_x2[gidx];
}

// ---------------- head 2 ----------------
__global__ void k_mlp(const float* __restrict__ feat, const float* __restrict__ Wf1,
                      const float* __restrict__ bf1, const float* __restrict__ Wf2,
                      const float* __restrict__ bf2, int gcount, int featd) {
    __shared__ __align__(16) float fs[8 * 1024];
    __shared__ float part[128 * 8];
    __shared__ float red[8][4];
    int g0 = blockIdx.x * 8;
    int tid = threadIdx.x;

    for (int idx = tid; idx < 8 * featd; idx += 256) {
        int k = idx >> 3, gg = idx & 7;
        fs[idx] = (g0 + gg < gcount) ? feat[(size_t)(g0 + gg) * featd + k] : 0.f;
    }
    __syncthreads();

    int hid = tid & 127;
    int half = tid >> 7;
    int k0 = half ? (featd / 2) : 0;
    int k1 = half ? featd : (featd / 2);

    float acc[8];
    #pragma unroll
    for (int gg = 0; gg < 8; gg++) acc[gg] = 0.f;

    #pragma unroll 4
    for (int k = k0; k < k1; k++) {
        float wv = Wf1[(size_t)k * 128 + hid];
        float4 f0 = *(const float4*)&fs[k * 8];
        float4 f1 = *(const float4*)&fs[k * 8 + 4];
        acc[0] += f0.x * wv; acc[1] += f0.y * wv;
        acc[2] += f0.z * wv; acc[3] += f0.w * wv;
        acc[4] += f1.x * wv; acc[5] += f1.y * wv;
        acc[6] += f1.z * wv; acc[7] += f1.w * wv;
    }

    if (half == 1) {
        #pragma unroll
        for (int gg = 0; gg < 8; gg++) part[hid * 8 + gg] = acc[gg];
    }
    __syncthreads();

    if (half == 0) {
        float b1v = bf1[hid];
        float w2v = Wf2[hid];
        int lane = hid & 31, w = hid >> 5;
        #pragma unroll
        for (int gg = 0; gg < 8; gg++) {
            float v = fmaxf(acc[gg] + part[hid * 8 + gg] + b1v, 0.f) * w2v;
            #pragma unroll
            for (int o = 16; o; o >>= 1) v += __shfl_down_sync(0xffffffffu, v, o);
            if (lane == 0) red[gg][w] = v;
        }
    }
    __syncthreads();
    if (tid < 8 && g0 + tid < gcount)
        g_x2[g0 + tid] = red[tid][0] + red[tid][1] + red[tid][2] + red[tid][3] + bf2[0];
}

// ---------------- launch ----------------
extern "C" void kernel_launch(void* const* d_in, const int* in_sizes, int n_in,
                              void* d_out, int out_size) {
    const float* x       = (const float*)d_in[0];
    const int*   ei      = (const int*)d_in[1];
    const int*   batch   = (const int*)d_in[2];
    const float* feature = (const float*)d_in[3];
    const float* W1 = (const float*)d_in[4];
    const float* b1 = (const float*)d_in[5];
    const float* W2 = (const float*)d_in[6];
    const float* b2 = (const float*)d_in[7];
    const float* W3 = (const float*)d_in[8];
    const float* b3 = (const float*)d_in[9];
    const float* Wg = (const float*)d_in[10];
    const float* bg = (const float*)d_in[11];
    const float* Wf1 = (const float*)d_in[12];
    const float* bf1 = (const float*)d_in[13];
    const float* Wf2 = (const float*)d_in[14];
    const float* bf2 = (const float*)d_in[15];
    float* out = (float*)d_out;

    int n = in_sizes[2];           // N nodes
    int e = in_sizes[1] / 2;       // E edges
    int g = out_size;              // G graphs
    int featd = in_sizes[3] / g;   // FEAT

    const int* src = ei;
    const int* dst = ei + e;

    float *pA, *pB;
    cudaGetSymbolAddress((void**)&pA, g_bufA);
    cudaGetSymbolAddress((void**)&pB, g_bufB);

    int nb  = (n + 1023) / 1024;
    int gb1 = (n + 127) / 128;     // gemm NPB=128
    int gb3 = (n + 63) / 64;       // gemm NPB=64 (layer 3, smem limit)
    int ab1 = (n + 15) / 16;       // agg44
    int ab2 = (n + 7) / 8;         // agg88

    // gemm1 (CSR-independent) at launch index 3: ncu's fixed capture slot lands
    // on the new f32x2 GEMM so this round's profile verifies the rewrite.
    k_deg<<<(e + 255) / 256, 256>>>(dst, e);                 // 0
    k_scanA<<<nb, 1024>>>(n);                                // 1
    k_scanB<<<1, 128>>>(nb);                                 // 2
    k_gemm2<44, 44, 0, 128><<<gb1, 128>>>(x, W1, pA, n);     // 3  <- profiled
    k_scanC<<<nb, 1024>>>(n, e);                             // 4
    k_fill<<<(e + 255) / 256, 256>>>(src, dst, e);           // 5

    // GCN layers
    k_agg44<1><<<ab1, 256>>>(pA, b1, pB, n, 1);              // 6 (applies dinv[src])
    k_gemm2<44, 88, 1, 128><<<gb1, 128>>>(pB, W2, pA, n);    // 7
    k_agg88<<<ab2, 256>>>(pA, b2, pB, n);                    // 8
    k_gemm2<88, 44, 1, 64><<<gb3, 64>>>(pB, W3, pA, n);      // 9
    k_agg44<0><<<ab1, 256>>>(pA, b3, pB, n, 0);              // 10

    // heads
    k_mlp<<<(g + 7) / 8, 256>>>(feature, Wf1, bf1, Wf2, bf2, g, featd);  // 11
    k_poolx1<<<(g + 7) / 8, 256>>>(batch, pB, Wg, bg, out, n, g);        // 12
}

// round 16
// speedup vs baseline: 1.2441x; 1.0179x over previous
#include <cuda_runtime.h>
#include <cstdint>

// Problem-shape constants (fixed by the dataset)
#define NN     100000
#define EE     1000000
#define GGR    1024
#define FF     44
#define HMAX   88

// ---------------- scratch (static __device__, zero-initialized at load) ----------------
__device__ int   g_cnt[NN];       // zeroed at load; re-zeroed by agg1 each launch
__device__ int   g_cur[NN];       // same
__device__ int   g_rowptr[NN + 1];
__device__ int   g_col[EE];
__device__ float g_dinv[NN];
__device__ __align__(16) float g_bufA[(size_t)NN * HMAX];
__device__ __align__(16) float g_bufB[(size_t)NN * HMAX];
__device__ float g_x2[GGR];
__device__ int   g_bsum[128];

// ---------------- CSR build ----------------
__global__ void k_deg(const int* __restrict__ dst, int e) {
    int i = blockIdx.x * blockDim.x + threadIdx.x;
    if (i < e) atomicAdd(&g_cnt[dst[i]], 1);
}

__global__ void k_scanA(int n) {
    __shared__ int s[1024];
    int t = threadIdx.x;
    int gid = blockIdx.x * 1024 + t;
    int v = (gid < n) ? g_cnt[gid] : 0;
    if (gid < n) g_dinv[gid] = rsqrtf((float)(v + 1));  // +1 self loop
    s[t] = v;
    __syncthreads();
    for (int off = 1; off < 1024; off <<= 1) {
        int x = (t >= off) ? s[t - off] : 0;
        __syncthreads();
        s[t] += x;
        __syncthreads();
    }
    if (gid < n) g_rowptr[gid] = s[t] - v;   // exclusive
    if (t == 1023) g_bsum[blockIdx.x] = s[1023];
}

__global__ void k_scanB(int nb) {
    int t = threadIdx.x;           // 128 threads
    int lane = t & 31, w = t >> 5;
    int v = (t < nb) ? g_bsum[t] : 0;
    int x = v;
    #pragma unroll
    for (int off = 1; off < 32; off <<= 1) {
        int y = __shfl_up_sync(0xffffffffu, x, off);
        if (lane >= off) x += y;
    }
    __shared__ int ws[4];
    if (lane == 31) ws[w] = x;
    __syncthreads();
    int add = 0;
    for (int i = 0; i < w; i++) add += ws[i];
    x += add;
    if (t < nb) g_bsum[t] = x - v;  // exclusive
}

__global__ void k_scanC(int n, int e) {
    int gid = blockIdx.x * 1024 + threadIdx.x;
    if (gid < n) g_rowptr[gid] += g_bsum[blockIdx.x];
    if (gid == 0) g_rowptr[n] = e;
}

__global__ void k_fill(const int* __restrict__ src, const int* __restrict__ dst, int e) {
    int i = blockIdx.x * blockDim.x + threadIdx.x;
    if (i < e) {
        int d = dst[i];
        int p = atomicAdd(&g_cur[d], 1);
        g_col[g_rowptr[d] + p] = src[i];
    }
}

// ---------------- GEMM, split-FOUT: 2 threads per node ----------------
// Thread (r, half) computes columns [half*FOUT/2, (half+1)*FOUT/2) for node r.
// x transposed in smem (padded stride); W in smem with 16B-aligned half rows;
// packed fma.rn.f32x2 accumulation.
// EPI: 0 = plain store, 1 = scale by dinv[node], 2 = relu(v + bias)
template <int FIN, int FOUT, int EPI, int NPB>
__global__ void __launch_bounds__(2 * NPB) k_gemm3(const float* __restrict__ in,
                                                   const float* __restrict__ W,
                                                   const float* __restrict__ bias,
                                                   float* __restrict__ out, int n) {
    constexpr int HALF  = FOUT / 2;             // columns per thread
    constexpr int HALFP = (HALF + 3) & ~3;      // padded to 16B multiple
    constexpr int NP2H  = HALF / 2;             // f32x2 accumulators per thread
    constexpr int F4    = FIN / 4;
    constexpr int XS    = NPB + 1;
    __shared__ __align__(16) float Ws[FIN * 2 * HALFP];
    __shared__ float xs[FIN * XS];

    int tid  = threadIdx.x;
    int r    = tid & (NPB - 1);
    int half = tid >= NPB;
    int node0 = blockIdx.x * NPB;

    // stage W: global [FIN][FOUT] row-major -> half-padded smem rows
    for (int idx = tid; idx < FIN * FOUT; idx += 2 * NPB) {
        int k = idx / FOUT, j = idx % FOUT;
        int h = j >= HALF;
        Ws[k * 2 * HALFP + h * HALFP + (j - h * HALF)] = W[idx];
    }

    // stage x transposed: xs[k * XS + rr] = in[node0 + rr][k]
    for (int f = tid; f < NPB * F4; f += 2 * NPB) {
        int rr = f / F4, c4 = f % F4;
        int node = node0 + rr;
        float4 v = (node < n) ? ((const float4*)in)[(size_t)node * F4 + c4]
                              : make_float4(0.f, 0.f, 0.f, 0.f);
        xs[(c4 * 4 + 0) * XS + rr] = v.x;
        xs[(c4 * 4 + 1) * XS + rr] = v.y;
        xs[(c4 * 4 + 2) * XS + rr] = v.z;
        xs[(c4 * 4 + 3) * XS + rr] = v.w;
    }
    __syncthreads();

    unsigned long long acc[NP2H];
    #pragma unroll
    for (int j = 0; j < NP2H; j++) acc[j] = 0ULL;

    const float* wbase0 = Ws + half * HALFP;
    #pragma unroll 4
    for (int k = 0; k < FIN; k++) {
        float xk = xs[k * XS + r];
        unsigned long long x2;
        asm("mov.b64 %0, {%1, %1};" : "=l"(x2) : "r"(__float_as_uint(xk)));
        const ulonglong2* wrow = (const ulonglong2*)(wbase0 + k * 2 * HALFP);
        #pragma unroll
        for (int j2 = 0; j2 < (NP2H + 1) / 2; j2++) {
            ulonglong2 w = wrow[j2];
            asm("fma.rn.f32x2 %0, %1, %2, %0;" : "+l"(acc[2 * j2]) : "l"(x2), "l"(w.x));
            if (2 * j2 + 1 < NP2H)
                asm("fma.rn.f32x2 %0, %1, %2, %0;" : "+l"(acc[2 * j2 + 1]) : "l"(x2), "l"(w.y));
        }
    }

    int node = node0 + r;
    if (node < n) {
        float dv = (EPI == 1) ? g_dinv[node] : 1.f;
        float2* o2 = (float2*)(out + (size_t)node * FOUT + half * HALF);
        const float2* b2 = (const float2*)(bias + half * HALF);
        #pragma unroll
        for (int j = 0; j < NP2H; j++) {
            unsigned int a, b;
            asm("mov.b64 {%0,%1}, %2;" : "=r"(a), "=r"(b) : "l"(acc[j]));
            float2 v = make_float2(__uint_as_float(a), __uint_as_float(b));
            if (EPI == 1) { v.x *= dv; v.y *= dv; }
            if (EPI == 2) {
                float2 bb = b2[j];
                v.x = fmaxf(v.x + bb.x, 0.f);
                v.y = fmaxf(v.y + bb.y, 0.f);
            }
            o2[j] = v;
        }
    }
}

// ---------------- aggregation, width 44: 2 nodes per warp ----------------
// SRCSCALE=1: gathered rows are UNscaled; multiply each by dinv[src].
// BIASRELU=1: out = relu(dinv[i]*acc + b); BIASRELU=0: out = dinv[i]*acc.
template <int SRCSCALE, int BIASRELU>
__global__ void k_agg44(const float* __restrict__ g, const float* __restrict__ bias,
                        float* __restrict__ out, int n, int clean) {
    constexpr int NV = 11;                 // 44 floats = 11 float4
    int warp = threadIdx.x >> 5;
    int lane = threadIdx.x & 31;
    int half = lane >> 4;
    int hl   = lane & 15;
    int node = blockIdx.x * 16 + warp * 2 + half;
    if (node >= n) return;
    if (clean && hl == 0) { g_cnt[node] = 0; g_cur[node] = 0; }  // reset for replays
    if (hl >= NV) return;

    int beg = g_rowptr[node];
    int end = g_rowptr[node + 1];

    const float4* g4 = (const float4*)g;
    float dvn = g_dinv[node];
    float4 acc = g4[(size_t)node * NV + hl];          // self-loop term
    if (SRCSCALE) { acc.x *= dvn; acc.y *= dvn; acc.z *= dvn; acc.w *= dvn; }

    int e = beg;
    for (; e + 4 <= end; e += 4) {
        int s0 = g_col[e + 0], s1 = g_col[e + 1], s2 = g_col[e + 2], s3 = g_col[e + 3];
        float4 v0 = g4[(size_t)s0 * NV + hl];
        float4 v1 = g4[(size_t)s1 * NV + hl];
        float4 v2 = g4[(size_t)s2 * NV + hl];
        float4 v3 = g4[(size_t)s3 * NV + hl];
        if (SRCSCALE) {
            float d0 = g_dinv[s0], d1 = g_dinv[s1], d2 = g_dinv[s2], d3 = g_dinv[s3];
            acc.x += (d0 * v0.x + d1 * v1.x) + (d2 * v2.x + d3 * v3.x);
            acc.y += (d0 * v0.y + d1 * v1.y) + (d2 * v2.y + d3 * v3.y);
            acc.z += (d0 * v0.z + d1 * v1.z) + (d2 * v2.z + d3 * v3.z);
            acc.w += (d0 * v0.w + d1 * v1.w) + (d2 * v2.w + d3 * v3.w);
        } else {
            acc.x += (v0.x + v1.x) + (v2.x + v3.x);
            acc.y += (v0.y + v1.y) + (v2.y + v3.y);
            acc.z += (v0.z + v1.z) + (v2.z + v3.z);
            acc.w += (v0.w + v1.w) + (v2.w + v3.w);
        }
    }
    for (; e < end; e++) {
        int s = g_col[e];
        float4 v = g4[(size_t)s * NV + hl];
        float d = SRCSCALE ? g_dinv[s] : 1.f;
        acc.x += d * v.x; acc.y += d * v.y; acc.z += d * v.z; acc.w += d * v.w;
    }
    float4 o;
    if (BIASRELU) {
        float4 b = ((const float4*)bias)[hl];
        o.x = fmaxf(dvn * acc.x + b.x, 0.f);
        o.y = fmaxf(dvn * acc.y + b.y, 0.f);
        o.z = fmaxf(dvn * acc.z + b.z, 0.f);
        o.w = fmaxf(dvn * acc.w + b.w, 0.f);
    } else {
        o.x = dvn * acc.x; o.y = dvn * acc.y;
        o.z = dvn * acc.z; o.w = dvn * acc.w;
    }
    ((float4*)out)[(size_t)node * NV + hl] = o;
}

// ---------------- fused pool + head1 + combine ----------------
__device__ __forceinline__ int lower_bound_dev(const int* a, int n, int key) {
    int lo = 0, hi = n;
    while (lo < hi) {
        int m = (lo + hi) >> 1;
        if (a[m] < key) lo = m + 1; else hi = m;
    }
    return lo;
}

__global__ void k_poolx1(const int* __restrict__ batch, const float* __restrict__ h,
                         const float* __restrict__ Wg, const float* __restrict__ bg,
                         float* __restrict__ out, int n, int gcount) {
    constexpr int NV = FF / 4;  // 11
    int warp = threadIdx.x >> 5;
    int lane = threadIdx.x & 31;
    int gidx = blockIdx.x * 8 + warp;
    if (gidx >= gcount) return;

    int beg = lower_bound_dev(batch, n, gidx);
    int end = lower_bound_dev(batch, n, gidx + 1);

    float part = 0.f;
    if (lane < NV) {
        const float4* h4 = (const float4*)h;
        float4 m = make_float4(0.f, 0.f, 0.f, 0.f);
        int r = beg;
        for (; r + 2 <= end; r += 2) {
            float4 v0 = h4[(size_t)r * NV + lane];
            float4 v1 = h4[(size_t)(r + 1) * NV + lane];
            m.x = fmaxf(m.x, fmaxf(v0.x, v1.x));
            m.y = fmaxf(m.y, fmaxf(v0.y, v1.y));
            m.z = fmaxf(m.z, fmaxf(v0.z, v1.z));
            m.w = fmaxf(m.w, fmaxf(v0.w, v1.w));
        }
        for (; r < end; r++) {
            float4 v = h4[(size_t)r * NV + lane];
            m.x = fmaxf(m.x, v.x); m.y = fmaxf(m.y, v.y);
            m.z = fmaxf(m.z, v.z); m.w = fmaxf(m.w, v.w);
        }
        float4 w4 = ((const float4*)Wg)[lane];
        part = m.x * w4.x + m.y * w4.y + m.z * w4.z + m.w * w4.w;
    }
    #pragma unroll
    for (int o = 16; o; o >>= 1) part += __shfl_down_sync(0xffffffffu, part, o);
    if (lane == 0) out[gidx] = fmaxf(part + bg[0], 0.f) + g_x2[gidx];
}

// ---------------- head 2 ----------------
__global__ void k_mlp(const float* __restrict__ feat, const float* __restrict__ Wf1,
                      const float* __restrict__ bf1, const float* __restrict__ Wf2,
                      const float* __restrict__ bf2, int gcount, int featd) {
    __shared__ __align__(16) float fs[8 * 1024];
    __shared__ float part[128 * 8];
    __shared__ float red[8][4];
    int g0 = blockIdx.x * 8;
    int tid = threadIdx.x;

    for (int idx = tid; idx < 8 * featd; idx += 256) {
        int k = idx >> 3, gg = idx & 7;
        fs[idx] = (g0 + gg < gcount) ? feat[(size_t)(g0 + gg) * featd + k] : 0.f;
    }
    __syncthreads();

    int hid = tid & 127;
    int half = tid >> 7;
    int k0 = half ? (featd / 2) : 0;
    int k1 = half ? featd : (featd / 2);

    float acc[8];
    #pragma unroll
    for (int gg = 0; gg < 8; gg++) acc[gg] = 0.f;

    #pragma unroll 4
    for (int k = k0; k < k1; k++) {
        float wv = Wf1[(size_t)k * 128 + hid];
        float4 f0 = *(const float4*)&fs[k * 8];
        float4 f1 = *(const float4*)&fs[k * 8 + 4];
        acc[0] += f0.x * wv; acc[1] += f0.y * wv;
        acc[2] += f0.z * wv; acc[3] += f0.w * wv;
        acc[4] += f1.x * wv; acc[5] += f1.y * wv;
        acc[6] += f1.z * wv; acc[7] += f1.w * wv;
    }

    if (half == 1) {
        #pragma unroll
        for (int gg = 0; gg < 8; gg++) part[hid * 8 + gg] = acc[gg];
    }
    __syncthreads();

    if (half == 0) {
        float b1v = bf1[hid];
        float w2v = Wf2[hid];
        int lane = hid & 31, w = hid >> 5;
        #pragma unroll
        for (int gg = 0; gg < 8; gg++) {
            float v = fmaxf(acc[gg] + part[hid * 8 + gg] + b1v, 0.f) * w2v;
            #pragma unroll
            for (int o = 16; o; o >>= 1) v += __shfl_down_sync(0xffffffffu, v, o);
            if (lane == 0) red[gg][w] = v;
        }
    }
    __syncthreads();
    if (tid < 8 && g0 + tid < gcount)
        g_x2[g0 + tid] = red[tid][0] + red[tid][1] + red[tid][2] + red[tid][3] + bf2[0];
}

// ---------------- launch ----------------
extern "C" void kernel_launch(void* const* d_in, const int* in_sizes, int n_in,
                              void* d_out, int out_size) {
    const float* x       = (const float*)d_in[0];
    const int*   ei      = (const int*)d_in[1];
    const int*   batch   = (const int*)d_in[2];
    const float* feature = (const float*)d_in[3];
    const float* W1 = (const float*)d_in[4];
    const float* b1 = (const float*)d_in[5];
    const float* W2 = (const float*)d_in[6];
    const float* b2 = (const float*)d_in[7];
    const float* W3 = (const float*)d_in[8];
    const float* b3 = (const float*)d_in[9];
    const float* Wg = (const float*)d_in[10];
    const float* bg = (const float*)d_in[11];
    const float* Wf1 = (const float*)d_in[12];
    const float* bf1 = (const float*)d_in[13];
    const float* Wf2 = (const float*)d_in[14];
    const float* bf2 = (const float*)d_in[15];
    float* out = (float*)d_out;

    int n = in_sizes[2];           // N nodes
    int e = in_sizes[1] / 2;       // E edges
    int g = out_size;              // G graphs
    int featd = in_sizes[3] / g;   // FEAT

    const int* src = ei;
    const int* dst = ei + e;

    float *pA, *pB;
    cudaGetSymbolAddress((void**)&pA, g_bufA);
    cudaGetSymbolAddress((void**)&pB, g_bufB);

    int nb  = (n + 1023) / 1024;
    int gb128 = (n + 127) / 128;   // gemm NPB=128 (256 threads)
    int gb64  = (n + 63) / 64;     // gemm NPB=64 (128 threads, layer 3 smem)
    int ab  = (n + 15) / 16;       // agg44: 16 nodes per block

    // gemm1 (CSR-independent) at launch index 3: ncu's fixed capture slot lands
    // on the new split-FOUT GEMM so this round's profile verifies the rewrite.
    k_deg<<<(e + 255) / 256, 256>>>(dst, e);                         // 0
    k_scanA<<<nb, 1024>>>(n);                                        // 1
    k_scanB<<<1, 128>>>(nb);                                         // 2
    k_gemm3<44, 44, 0, 128><<<gb128, 256>>>(x, W1, b1, pA, n);       // 3  <- profiled
    k_scanC<<<nb, 1024>>>(n, e);                                     // 4
    k_fill<<<(e + 255) / 256, 256>>>(src, dst, e);                   // 5

    // Layer 1: gemm-first. h1 = relu(dinv*(sum dinv[s]*g[s] + dinv*g[i]) + b1)
    k_agg44<1, 1><<<ab, 256>>>(pA, b1, pB, n, 1);                    // 6
    // Layer 2: agg-first (agg and GEMM commute). a2 = normalized agg of h1 (44-wide),
    // then h2 = relu(a2 @ W2 + b2) with fused epilogue.
    k_agg44<1, 0><<<ab, 256>>>(pB, b2, pA, n, 0);                    // 7
    k_gemm3<44, 88, 2, 128><<<gb128, 256>>>(pA, W2, b2, pB, n);      // 8
    // Layer 3: gemm-first (agg at 44-wide). g3 = dinv*(h2 @ W3); h3 = relu(agg+b3)
    k_gemm3<88, 44, 1, 64><<<gb64, 128>>>(pB, W3, b3, pA, n);        // 9
    k_agg44<0, 1><<<ab, 256>>>(pA, b3, pB, n, 0);                    // 10

    // heads
    k_mlp<<<(g + 7) / 8, 256>>>(feature, Wf1, bf1, Wf2, bf2, g, featd);  // 11
    k_poolx1<<<(g + 7) / 8, 256>>>(batch, pB, Wg, bg, out, n, g);        // 12
}